// round 8
// baseline (speedup 1.0000x reference)
#include <cuda_runtime.h>
#include <cuda_bf16.h>
#include <mma.h>
#include <cstdint>

using namespace nvcuda;

#define BATCH 2
#define APTS 20000
#define BN 1024
#define NNEI 192
#define GNUM 64
#define GPB 4   // grasps per bq block

static __device__ float4 g_p4[BATCH*APTS];                 // x,y,z,|x|^2
static __device__ float  g_RtC[BN][12];
static __device__ int    g_gmask[BN];
static __device__ float  g_gpts[BN*GNUM*3];
static __device__ __nv_bfloat16 g_W2tb[512*256];           // k-major [k][o]
static __device__ __nv_bfloat16 g_W3tb[256*256];
static __device__ __nv_bfloat16 g_W4tb[256*128];
static __device__ float  g_h2[BN*64*256];                  // raw (pre-bias/relu) f32
static __device__ float  g_h3[BN*64*256];                  // raw f32

// ---------------- prep kernels ----------------

__global__ void prep_points(const float* __restrict__ pc) {
  int i = blockIdx.x*blockDim.x + threadIdx.x;
  if (i >= BATCH*APTS) return;
  float x = pc[i*6+0], y = pc[i*6+1], z = pc[i*6+2];
  float xx = __fadd_rn(__fadd_rn(__fmul_rn(x,x),__fmul_rn(y,y)),__fmul_rn(z,z));
  g_p4[i] = make_float4(x,y,z,xx);
}

__global__ void prep_grasp(const float* __restrict__ grasp) {
  int g = blockIdx.x*blockDim.x + threadIdx.x;
  if (g >= BN) return;
  const float* gr = grasp + g*8;
  float s8 = 0.f;
  for (int k=0;k<8;k++) s8 += gr[k];
  g_gmask[g] = (s8 != -8.0f) ? 1 : 0;
  float cx=gr[0], cy=gr[1], cz=gr[2];
  float ay0=gr[3], ay1=gr[4], ay2=gr[5];
  float ang=gr[6];
  float c=cosf(ang), s=sinf(ang);
  float ny = sqrtf(ay0*ay0+ay1*ay1+ay2*ay2);
  ay0 = ay0/(ny+1e-12f); ay1 = ay1/(ny+1e-12f); ay2 = ay2/(ny+1e-12f);
  float ax0=ay1, ax1=-ay0;
  float nx = sqrtf(ax0*ax0+ax1*ax1);
  ax0 = ax0/(nx+1e-12f); ax1 = ax1/(nx+1e-12f);
  float az0 = ax1*ay2;
  float az1 = -ax0*ay2;
  float az2 = ax0*ay1 - ax1*ay0;
  float nz = sqrtf(az0*az0+az1*az1+az2*az2);
  if (nz == 0.0f) { az0=0.f; az1=0.f; az2=1.f; }
  else { az0/=nz; az1/=nz; az2/=nz; }
  float ap0 = c*ax0 + s*az0;
  float ap1 = c*ax1 + s*az1;
  float ap2 = s*az2;
  float na = sqrtf(ap0*ap0+ap1*ap1+ap2*ap2);
  ap0 = ap0/(na+1e-12f); ap1 = ap1/(na+1e-12f); ap2 = ap2/(na+1e-12f);
  float mn0 = ap1*ay2 - ap2*ay1;
  float mn1 = ap2*ay0 - ap0*ay2;
  float mn2 = ap0*ay1 - ap1*ay0;
  float* R = g_RtC[g];
  R[0]=ap0; R[1]=ap1; R[2]=ap2;
  R[3]=ay0; R[4]=ay1; R[5]=ay2;
  R[6]=mn0; R[7]=mn1; R[8]=mn2;
  R[9]=cx;  R[10]=cy; R[11]=cz;
}

__global__ void transpose_w(const float* __restrict__ W2, const float* __restrict__ W3,
                            const float* __restrict__ W4) {
  int id = blockIdx.x*blockDim.x + threadIdx.x;
  if (id < 512*256) {
    int k = id >> 8, o = id & 255;
    g_W2tb[id] = __float2bfloat16(W2[o*512 + k]);
  } else if (id < 512*256 + 256*256) {
    int r = id - 512*256;
    int k = r >> 8, o = r & 255;
    g_W3tb[r] = __float2bfloat16(W3[o*256 + k]);
  } else if (id < 512*256 + 256*256 + 256*128) {
    int r = id - (512*256 + 256*256);
    int k = r >> 7, o = r & 127;
    g_W4tb[r] = __float2bfloat16(W4[o*256 + k]);
  }
}

// ---------------- ball query + gripper transform + selection ----------------
// 256 thr = 8 warps; each block handles GPB=4 grasps sharing one point scan.

__global__ void __launch_bounds__(256) bq_kernel(const float* __restrict__ grasp,
                                                 float* __restrict__ out) {
  __shared__ int s_list[GPB][8][NNEI];     // 24576 B
  __shared__ int s_app[GPB][8], s_tot[GPB][8];
  __shared__ float s_c[GPB][4];
  __shared__ int s_nbr[NNEI];
  __shared__ float s_t[NNEI][3];
  __shared__ unsigned char s_in[NNEI];
  __shared__ int s_sel[GNUM];
  __shared__ int s_totvalid, s_ccount;
  __shared__ float s_R[12];

  int g0 = blockIdx.x*GPB;
  int b = g0 >> 9;         // all 4 grasps in same batch (512 % 4 == 0)
  int tx = threadIdx.x;
  int w = tx >> 5, lane = tx & 31;

  if (tx < GPB) {
    const float* gr = grasp + (g0+tx)*8;
    float cx=gr[0], cy=gr[1], cz=gr[2];
    s_c[tx][0]=cx; s_c[tx][1]=cy; s_c[tx][2]=cz;
    s_c[tx][3] = __fadd_rn(__fadd_rn(__fmul_rn(cx,cx),__fmul_rn(cy,cy)),__fmul_rn(cz,cz));
  }
  __syncthreads();

  float cxr[GPB], cyr[GPB], czr[GPB], ccr[GPB];
  #pragma unroll
  for (int gi=0; gi<GPB; gi++) {
    cxr[gi]=s_c[gi][0]; cyr[gi]=s_c[gi][1]; czr[gi]=s_c[gi][2]; ccr[gi]=s_c[gi][3];
  }

  const int chunk = APTS/8; // 2500
  int lo = b*APTS + w*chunk, hi = lo + chunk;
  int tot[GPB], app[GPB];
  #pragma unroll
  for (int gi=0; gi<GPB; gi++) { tot[gi]=0; app[gi]=0; }

  for (int base=lo; base<hi; base+=32) {
    int i = base + lane;
    float4 p = make_float4(0.f,0.f,0.f,1e30f);
    bool inb = (i < hi);
    if (inb) p = g_p4[i];
    #pragma unroll
    for (int gi=0; gi<GPB; gi++) {
      bool ok=false;
      if (inb) {
        float dot = __fadd_rn(__fadd_rn(__fmul_rn(cxr[gi],p.x),__fmul_rn(cyr[gi],p.y)),
                              __fmul_rn(czr[gi],p.z));
        float d2 = __fsub_rn(__fadd_rn(ccr[gi], p.w), __fmul_rn(2.0f,dot));
        ok = d2 < 0.09f;
      }
      unsigned mb = __ballot_sync(0xffffffffu, ok);
      if (ok) {
        int pos = app[gi] + __popc(mb & ((1u<<lane)-1u));
        if (pos < NNEI) s_list[gi][w][pos] = i - b*APTS;
      }
      tot[gi] += __popc(mb);
      app[gi] = tot[gi] < NNEI ? tot[gi] : NNEI;
    }
  }
  if (lane==0) {
    #pragma unroll
    for (int gi=0; gi<GPB; gi++) { s_app[gi][w]=app[gi]; s_tot[gi][w]=tot[gi]; }
  }

  // tail phases, one grasp at a time
  for (int gi=0; gi<GPB; gi++) {
    int g = g0 + gi;
    __syncthreads();
    if (tx==0) {
      int totv = 0;
      for (int ww=0; ww<8; ww++) totv += s_tot[gi][ww];
      int run=0;
      for (int ww=0; ww<8 && run<NNEI; ww++) {
        int t = s_app[gi][ww]; if (t > NNEI-run) t = NNEI-run;
        for (int j=0;j<t;j++) s_nbr[run+j] = s_list[gi][ww][j];
        run += t;
      }
      int pad = (run>0) ? s_nbr[0] : 0;
      for (int j=run;j<NNEI;j++) s_nbr[j]=pad;
      s_totvalid = totv;
    }
    if (tx >= 32 && tx < 44) s_R[tx-32] = g_RtC[g][tx-32];
    __syncthreads();

    for (int p=tx; p<NNEI; p+=blockDim.x) {
      float4 pt = g_p4[b*APTS + s_nbr[p]];
      float vx = pt.x-s_R[9], vy = pt.y-s_R[10], vz = pt.z-s_R[11];
      float t0 = s_R[0]*vx + s_R[1]*vy + s_R[2]*vz;
      float t1 = s_R[3]*vx + s_R[4]*vy + s_R[5]*vz;
      float t2 = s_R[6]*vx + s_R[7]*vy + s_R[8]*vz;
      s_t[p][0]=t0; s_t[p][1]=t1; s_t[p][2]=t2;
      bool ins = (t0>0.0f)&&(t0<0.3f)&&(t1>-0.15f)&&(t1<0.15f)&&(t2>-0.1f)&&(t2<0.1f);
      s_in[p] = ins ? 1 : 0;
    }
    __syncthreads();

    if (tx < 32) {
      int totI=0, first=-1;
      for (int ch=0; ch<NNEI/32; ch++) {
        int p = ch*32 + lane;
        bool ok = s_in[p]!=0;
        unsigned mm = __ballot_sync(0xffffffffu, ok);
        int app64 = totI<GNUM ? totI : GNUM;
        if (ok) {
          int pos = app64 + __popc(mm & ((1u<<lane)-1u));
          if (pos < GNUM) s_sel[pos] = p;
        }
        if (first<0 && mm) first = ch*32 + __ffs(mm)-1;
        totI += __popc(mm);
      }
      int cc64 = totI<GNUM ? totI : GNUM;
      int pad = (totI>0) ? first : 0;
      for (int j=lane; j<GNUM; j+=32) if (j>=cc64) s_sel[j]=pad;
      if (lane==0) s_ccount = cc64;
    }
    __syncthreads();

    for (int idx=tx; idx<GNUM*3; idx+=blockDim.x) {
      int n = idx/3, d = idx - n*3;
      g_gpts[g*(GNUM*3)+idx] = s_t[s_sel[n]][d];
    }
    if (tx==0) {
      bool mk = (s_totvalid>0) && (s_ccount>0) && (g_gmask[g]!=0);
      out[10240 + g] = mk ? 1.0f : 0.0f;
    }
  }
}

// ---------------- layer 1+2 fused (wmma bf16): raw h2 = h1 @ W2t ----------------
// 2 grasps/block (M=128), 8 warps: m0=(wid&3)*32, n0=(wid>>2)*128. K-chunk 32.

#define APAD 40
#define BPAD 264

__global__ void __launch_bounds__(256) layer12_kernel(
  const float* __restrict__ W1, const float* __restrict__ b1)
{
  __shared__ alignas(32) __nv_bfloat16 s_a[128*APAD];   // 10240 B
  __shared__ alignas(32) __nv_bfloat16 s_b[32*BPAD];    // 16896 B
  __shared__ float s_pts[2*GNUM*3];
  int tx = threadIdx.x;
  int g0 = blockIdx.x*2;
  int wid = tx >> 5;
  for (int i=tx; i<2*GNUM*3; i+=256) s_pts[i] = g_gpts[g0*(GNUM*3)+i];

  wmma::fragment<wmma::accumulator,16,16,16,float> acc[2][8];
  #pragma unroll
  for (int mi=0;mi<2;mi++)
    #pragma unroll
    for (int f=0;f<8;f++) wmma::fill_fragment(acc[mi][f], 0.0f);
  int m0 = (wid & 3) * 32;
  int n0 = (wid >> 2) * 128;

  int kl = tx & 31;
  int nb = tx >> 5;            // 8 groups of 16 rows
  __syncthreads();

  for (int kt=0; kt<16; kt++) {
    // stage B tile [32][256] bf16
    #pragma unroll
    for (int t=0;t<4;t++) {
      int idx = tx + 256*t;
      int r = idx >> 5, c8 = idx & 31;
      reinterpret_cast<uint4*>(s_b + r*BPAD)[c8] =
        reinterpret_cast<const uint4*>(g_W2tb + (kt*32 + r)*256)[c8];
    }
    // compute h1 tile [128][32]
    int k = kt*32 + kl;
    float w0=W1[k*3], w1=W1[k*3+1], w2=W1[k*3+2], bb1=b1[k];
    #pragma unroll
    for (int t=0;t<16;t++) {
      int n = nb*16 + t;
      const float* pp = s_pts + (n>>6)*(GNUM*3) + (n&63)*3;
      float v = fmaf(w2, pp[2], fmaf(w1, pp[1], fmaf(w0, pp[0], bb1)));
      s_a[n*APAD + kl] = __float2bfloat16(v>0.f ? v : 0.f);
    }
    __syncthreads();
    #pragma unroll
    for (int ks=0; ks<2; ks++) {
      wmma::fragment<wmma::matrix_a,16,16,16,__nv_bfloat16,wmma::row_major> fa[2];
      #pragma unroll
      for (int mi=0;mi<2;mi++)
        wmma::load_matrix_sync(fa[mi], s_a + (m0+16*mi)*APAD + ks*16, APAD);
      #pragma unroll
      for (int f=0;f<8;f++) {
        wmma::fragment<wmma::matrix_b,16,16,16,__nv_bfloat16,wmma::row_major> fb;
        wmma::load_matrix_sync(fb, s_b + (ks*16)*BPAD + n0 + 16*f, BPAD);
        #pragma unroll
        for (int mi=0;mi<2;mi++) wmma::mma_sync(acc[mi][f], fa[mi], fb, acc[mi][f]);
      }
    }
    __syncthreads();
  }
  #pragma unroll
  for (int mi=0;mi<2;mi++) {
    int mrow = m0 + 16*mi;
    float* dst = g_h2 + (g0 + (mrow>>6))*16384 + (mrow&63)*256;
    #pragma unroll
    for (int f=0;f<8;f++)
      wmma::store_matrix_sync(dst + n0 + 16*f, acc[mi][f], 256, wmma::mem_row_major);
  }
}

// ---------------- layer 3 (wmma): raw h3 = relu(h2+b2) @ W3t ----------------

__global__ void __launch_bounds__(256) layer3_kernel(const float* __restrict__ b2)
{
  __shared__ alignas(32) __nv_bfloat16 s_a[128*APAD];
  __shared__ alignas(32) __nv_bfloat16 s_b[32*BPAD];
  int tx = threadIdx.x;
  int g0 = blockIdx.x*2;
  int wid = tx >> 5;
  wmma::fragment<wmma::accumulator,16,16,16,float> acc[2][8];
  #pragma unroll
  for (int mi=0;mi<2;mi++)
    #pragma unroll
    for (int f=0;f<8;f++) wmma::fill_fragment(acc[mi][f], 0.0f);
  int m0 = (wid & 3) * 32;
  int n0 = (wid >> 2) * 128;
  int kl = tx & 31;
  int nb = tx >> 5;

  for (int kt=0; kt<8; kt++) {
    #pragma unroll
    for (int t=0;t<4;t++) {
      int idx = tx + 256*t;
      int r = idx >> 5, c8 = idx & 31;
      reinterpret_cast<uint4*>(s_b + r*BPAD)[c8] =
        reinterpret_cast<const uint4*>(g_W3tb + (kt*32 + r)*256)[c8];
    }
    int k = kt*32 + kl;
    float bb = b2[k];
    #pragma unroll
    for (int t=0;t<16;t++) {
      int n = nb*16 + t;
      float v = g_h2[(g0 + (n>>6))*16384 + (n&63)*256 + k] + bb;
      s_a[n*APAD + kl] = __float2bfloat16(v>0.f ? v : 0.f);
    }
    __syncthreads();
    #pragma unroll
    for (int ks=0; ks<2; ks++) {
      wmma::fragment<wmma::matrix_a,16,16,16,__nv_bfloat16,wmma::row_major> fa[2];
      #pragma unroll
      for (int mi=0;mi<2;mi++)
        wmma::load_matrix_sync(fa[mi], s_a + (m0+16*mi)*APAD + ks*16, APAD);
      #pragma unroll
      for (int f=0;f<8;f++) {
        wmma::fragment<wmma::matrix_b,16,16,16,__nv_bfloat16,wmma::row_major> fb;
        wmma::load_matrix_sync(fb, s_b + (ks*16)*BPAD + n0 + 16*f, BPAD);
        #pragma unroll
        for (int mi=0;mi<2;mi++) wmma::mma_sync(acc[mi][f], fa[mi], fb, acc[mi][f]);
      }
    }
    __syncthreads();
  }
  #pragma unroll
  for (int mi=0;mi<2;mi++) {
    int mrow = m0 + 16*mi;
    float* dst = g_h3 + (g0 + (mrow>>6))*16384 + (mrow&63)*256;
    #pragma unroll
    for (int f=0;f<8;f++)
      wmma::store_matrix_sync(dst + n0 + 16*f, acc[mi][f], 256, wmma::mem_row_major);
  }
}

// ---------------- layer 4 + heads (1 grasp/block) ----------------

#define A4PAD 72
#define B4PAD 136
#define OPAD 132

__global__ void __launch_bounds__(256) layer4_heads_kernel(
  const float* __restrict__ b3, const float* __restrict__ b4,
  const float* __restrict__ stage1,
  const float* __restrict__ reg_w, const float* __restrict__ reg_b,
  const float* __restrict__ cls_w, const float* __restrict__ cls_b,
  const float* __restrict__ dc_reg_w, const float* __restrict__ dc_reg_b,
  const float* __restrict__ dc_cls_w, const float* __restrict__ dc_cls_b,
  float* __restrict__ out)
{
  __shared__ alignas(32) char s_mem[64*OPAD*4];   // staging (A+B bf16) then s_out f32
  __shared__ float s_hd[640 + 1280 + 80];
  __nv_bfloat16* s_a = reinterpret_cast<__nv_bfloat16*>(s_mem);                  // 64*72
  __nv_bfloat16* s_b = reinterpret_cast<__nv_bfloat16*>(s_mem) + 64*A4PAD;       // 64*136
  float* s_out = reinterpret_cast<float*>(s_mem);                                // 64*132

  int tx = threadIdx.x;
  int g = blockIdx.x;
  int wid = tx >> 5, lane = tx & 31;
  wmma::fragment<wmma::accumulator,16,16,16,float> acc[4];
  #pragma unroll
  for (int f=0;f<4;f++) wmma::fill_fragment(acc[f], 0.0f);
  int m0 = (wid & 3) * 16;
  int n0 = (wid >> 2) * 64;
  int kl = tx & 63;
  int nb = tx >> 6;

  float* s_dc  = s_hd;
  float* s_rw2 = s_hd + 640;
  float* s_pt  = s_hd + 1920;
  for (int i=tx;i<512;i+=256) s_dc[i]     = dc_reg_w[i];
  for (int i=tx;i<128;i+=256) s_dc[512+i] = dc_cls_w[i];
  for (int i=tx;i<1280;i+=256) {
    int c = i>>7, j = i&127;
    s_rw2[i] = (c<8) ? reg_w[c*384 + 256 + j] : cls_w[(c-8)*384 + 256 + j];
  }

  for (int kt=0; kt<4; kt++) {
    #pragma unroll
    for (int t=0;t<4;t++) {
      int idx = tx + 256*t;
      int r = idx >> 4, c8 = idx & 15;
      reinterpret_cast<uint4*>(s_b + r*B4PAD)[c8] =
        reinterpret_cast<const uint4*>(g_W4tb + (kt*64 + r)*128)[c8];
    }
    int k = kt*64 + kl;
    float bb = b3[k];
    #pragma unroll
    for (int t=0;t<16;t++) {
      int n = nb*16 + t;
      float v = g_h3[g*16384 + n*256 + k] + bb;
      s_a[n*A4PAD + kl] = __float2bfloat16(v>0.f ? v : 0.f);
    }
    __syncthreads();
    #pragma unroll
    for (int ks=0; ks<4; ks++) {
      wmma::fragment<wmma::matrix_a,16,16,16,__nv_bfloat16,wmma::row_major> fa;
      wmma::load_matrix_sync(fa, s_a + m0*A4PAD + ks*16, A4PAD);
      #pragma unroll
      for (int f=0;f<4;f++) {
        wmma::fragment<wmma::matrix_b,16,16,16,__nv_bfloat16,wmma::row_major> fb;
        wmma::load_matrix_sync(fb, s_b + (ks*16)*B4PAD + n0 + 16*f, B4PAD);
        wmma::mma_sync(acc[f], fa, fb, acc[f]);
      }
    }
    __syncthreads();
  }
  #pragma unroll
  for (int f=0;f<4;f++)
    wmma::store_matrix_sync(s_out + m0*OPAD + n0 + 16*f, acc[f], OPAD, wmma::mem_row_major);
  __syncthreads();

  int hn0 = wid*8, j0 = lane*4;
  float bj[4];
  #pragma unroll
  for (int q=0;q<4;q++) bj[q] = b4[j0+q];
  #pragma unroll
  for (int c=0;c<10;c++) {
    const float* dcw = (c<8) ? (s_dc + c*64) : (s_dc + 512 + (c-8)*64);
    const float* rw2 = s_rw2 + c*128 + j0;
    float pc_ = 0.f;
    #pragma unroll
    for (int i=0;i<8;i++) {
      float t = 0.f;
      #pragma unroll
      for (int q=0;q<4;q++) {
        float h = s_out[(hn0+i)*OPAD + j0+q] + bj[q];
        h = h>0.f ? h : 0.f;
        t = fmaf(rw2[q], h, t);
      }
      pc_ = fmaf(dcw[hn0+i], t, pc_);
    }
    #pragma unroll
    for (int off=16; off>0; off>>=1) pc_ += __shfl_down_sync(0xffffffffu, pc_, off);
    if (lane==0) s_pt[c*8 + wid] = pc_;
  }
  __syncthreads();

  for (int c = wid; c < 10; c += 8) {
    float hd = (lane < 8) ? s_pt[c*8 + lane] : 0.f;
    const float* rw = (c<8) ? (reg_w + c*384) : (cls_w + (c-8)*384);
    const float* s1 = stage1 + g*256;
    float s1d = 0.f;
    #pragma unroll
    for (int t=0;t<8;t++) {
      int j = lane + 32*t;
      s1d = fmaf(rw[j], s1[j], s1d);
    }
    const float* dcw = (c<8) ? (s_dc + c*64) : (s_dc + 512 + (c-8)*64);
    float S = dcw[lane] + dcw[lane+32];
    #pragma unroll
    for (int off=16; off>0; off>>=1) {
      hd  += __shfl_down_sync(0xffffffffu, hd,  off);
      s1d += __shfl_down_sync(0xffffffffu, s1d, off);
      S   += __shfl_down_sync(0xffffffffu, S,   off);
    }
    if (lane==0) {
      float bc  = (c<8) ? reg_b[c] : cls_b[c-8];
      float dcb = (c<8) ? dc_reg_b[c] : dc_cls_b[c-8];
      float o = hd + (s1d + bc)*S + dcb;
      if (c < 8) out[2048 + g*8 + c] = o;
      else       out[g*2 + (c-8)]   = o;
    }
  }
}

// ---------------- launch ----------------

extern "C" void kernel_launch(void* const* d_in, const int* in_sizes, int n_in,
                              void* d_out, int out_size) {
  const float* grasp  = (const float*)d_in[0];
  const float* pc     = (const float*)d_in[1];
  const float* stage1 = (const float*)d_in[3];
  const float* W1 = (const float*)d_in[4];  const float* b1 = (const float*)d_in[5];
  const float* W2 = (const float*)d_in[6];  const float* b2 = (const float*)d_in[7];
  const float* W3 = (const float*)d_in[8];  const float* b3 = (const float*)d_in[9];
  const float* W4 = (const float*)d_in[10]; const float* b4 = (const float*)d_in[11];
  const float* reg_w = (const float*)d_in[12]; const float* reg_b = (const float*)d_in[13];
  const float* cls_w = (const float*)d_in[14]; const float* cls_b = (const float*)d_in[15];
  const float* dcrw  = (const float*)d_in[16]; const float* dcrb  = (const float*)d_in[17];
  const float* dccw  = (const float*)d_in[18]; const float* dccb  = (const float*)d_in[19];
  float* out = (float*)d_out;

  prep_points<<<(BATCH*APTS + 255)/256, 256>>>(pc);
  prep_grasp<<<(BN + 255)/256, 256>>>(grasp);
  transpose_w<<<(512*256 + 256*256 + 256*128 + 255)/256, 256>>>(W2, W3, W4);
  bq_kernel<<<BN/GPB, 256>>>(grasp, out);
  layer12_kernel<<<BN/2, 256>>>(W1, b1);
  layer3_kernel<<<BN/2, 256>>>(b2);
  layer4_heads_kernel<<<BN, 256>>>(b3, b4, stage1, reg_w, reg_b, cls_w, cls_b,
                                   dcrw, dcrb, dccw, dccb, out);
}

// round 9
// speedup vs baseline: 1.2185x; 1.2185x over previous
#include <cuda_runtime.h>
#include <cuda_bf16.h>
#include <mma.h>
#include <cstdint>

using namespace nvcuda;

#define BATCH 2
#define APTS 20000
#define BN 1024
#define NNEI 192
#define GNUM 64

static __device__ float4 g_p4[BATCH*APTS];                 // x,y,z,|x|^2
static __device__ float  g_RtC[BN][12];
static __device__ int    g_gmask[BN];
static __device__ float  g_gpts[BN*GNUM*3];
static __device__ __nv_bfloat16 g_W2tb[512*256];           // k-major [k][o]
static __device__ __nv_bfloat16 g_W3tb[256*256];
static __device__ __nv_bfloat16 g_W4tb[256*128];

// ---------------- prep kernels ----------------

__global__ void prep_points(const float* __restrict__ pc) {
  int i = blockIdx.x*blockDim.x + threadIdx.x;
  if (i >= BATCH*APTS) return;
  float x = pc[i*6+0], y = pc[i*6+1], z = pc[i*6+2];
  float xx = __fadd_rn(__fadd_rn(__fmul_rn(x,x),__fmul_rn(y,y)),__fmul_rn(z,z));
  g_p4[i] = make_float4(x,y,z,xx);
}

__global__ void prep_grasp(const float* __restrict__ grasp) {
  int g = blockIdx.x*blockDim.x + threadIdx.x;
  if (g >= BN) return;
  const float* gr = grasp + g*8;
  float s8 = 0.f;
  for (int k=0;k<8;k++) s8 += gr[k];
  g_gmask[g] = (s8 != -8.0f) ? 1 : 0;
  float cx=gr[0], cy=gr[1], cz=gr[2];
  float ay0=gr[3], ay1=gr[4], ay2=gr[5];
  float ang=gr[6];
  float c=cosf(ang), s=sinf(ang);
  float ny = sqrtf(ay0*ay0+ay1*ay1+ay2*ay2);
  ay0 = ay0/(ny+1e-12f); ay1 = ay1/(ny+1e-12f); ay2 = ay2/(ny+1e-12f);
  float ax0=ay1, ax1=-ay0;
  float nx = sqrtf(ax0*ax0+ax1*ax1);
  ax0 = ax0/(nx+1e-12f); ax1 = ax1/(nx+1e-12f);
  float az0 = ax1*ay2;
  float az1 = -ax0*ay2;
  float az2 = ax0*ay1 - ax1*ay0;
  float nz = sqrtf(az0*az0+az1*az1+az2*az2);
  if (nz == 0.0f) { az0=0.f; az1=0.f; az2=1.f; }
  else { az0/=nz; az1/=nz; az2/=nz; }
  float ap0 = c*ax0 + s*az0;
  float ap1 = c*ax1 + s*az1;
  float ap2 = s*az2;
  float na = sqrtf(ap0*ap0+ap1*ap1+ap2*ap2);
  ap0 = ap0/(na+1e-12f); ap1 = ap1/(na+1e-12f); ap2 = ap2/(na+1e-12f);
  float mn0 = ap1*ay2 - ap2*ay1;
  float mn1 = ap2*ay0 - ap0*ay2;
  float mn2 = ap0*ay1 - ap1*ay0;
  float* R = g_RtC[g];
  R[0]=ap0; R[1]=ap1; R[2]=ap2;
  R[3]=ay0; R[4]=ay1; R[5]=ay2;
  R[6]=mn0; R[7]=mn1; R[8]=mn2;
  R[9]=cx;  R[10]=cy; R[11]=cz;
}

__global__ void transpose_w(const float* __restrict__ W2, const float* __restrict__ W3,
                            const float* __restrict__ W4) {
  int id = blockIdx.x*blockDim.x + threadIdx.x;
  if (id < 512*256) {
    int k = id >> 8, o = id & 255;
    g_W2tb[id] = __float2bfloat16(W2[o*512 + k]);
  } else if (id < 512*256 + 256*256) {
    int r = id - 512*256;
    int k = r >> 8, o = r & 255;
    g_W3tb[r] = __float2bfloat16(W3[o*256 + k]);
  } else if (id < 512*256 + 256*256 + 256*128) {
    int r = id - (512*256 + 256*256);
    int k = r >> 7, o = r & 127;
    g_W4tb[r] = __float2bfloat16(W4[o*256 + k]);
  }
}

// ---------------- ball query + gripper transform + selection ----------------
// 1 grasp/block, 8 warps x 2500 points; parallel list merge.

__global__ void __launch_bounds__(256) bq_kernel(const float* __restrict__ grasp,
                                                 float* __restrict__ out) {
  __shared__ int s_list[8][NNEI];
  __shared__ int s_app[8], s_tot[8];
  __shared__ int s_off[8], s_take[8];
  __shared__ int s_run, s_totvalid, s_ccount;
  __shared__ int s_nbr[NNEI];
  __shared__ float s_t[NNEI][3];
  __shared__ unsigned char s_in[NNEI];
  __shared__ int s_sel[GNUM];
  __shared__ float s_R[12];

  int g = blockIdx.x;
  int b = g >> 9;
  int tx = threadIdx.x;
  int w = tx >> 5, lane = tx & 31;
  const float* gr = grasp + g*8;
  float cx=gr[0], cy=gr[1], cz=gr[2];
  float cc = __fadd_rn(__fadd_rn(__fmul_rn(cx,cx),__fmul_rn(cy,cy)),__fmul_rn(cz,cz));
  if (tx < 12) s_R[tx] = g_RtC[g][tx];

  const int chunk = APTS/8; // 2500
  int lo = b*APTS + w*chunk, hi = lo + chunk;
  int tot=0, app=0;
  for (int base=lo; base<hi; base+=32) {
    int i = base + lane;
    bool ok=false;
    if (i < hi) {
      float4 p = g_p4[i];
      float dot = __fadd_rn(__fadd_rn(__fmul_rn(cx,p.x),__fmul_rn(cy,p.y)),
                            __fmul_rn(cz,p.z));
      float d2 = __fsub_rn(__fadd_rn(cc, p.w), __fmul_rn(2.0f,dot));
      ok = d2 < 0.09f;
    }
    unsigned mb = __ballot_sync(0xffffffffu, ok);
    if (ok) {
      int pos = app + __popc(mb & ((1u<<lane)-1u));
      if (pos < NNEI) s_list[w][pos] = i - b*APTS;
    }
    tot += __popc(mb);
    app = tot < NNEI ? tot : NNEI;
  }
  if (lane==0) { s_app[w]=app; s_tot[w]=tot; }
  __syncthreads();

  if (tx==0) {
    int run=0, totv=0;
    for (int ww=0; ww<8; ww++) {
      totv += s_tot[ww];
      s_off[ww] = run;
      int t = s_app[ww];
      if (t > NNEI-run) t = NNEI-run;
      if (t < 0) t = 0;
      s_take[ww] = t;
      run += t;
    }
    s_run = run; s_totvalid = totv;
  }
  __syncthreads();

  // parallel merge: each warp copies its own list
  {
    int take = s_take[w], off = s_off[w];
    for (int j=lane; j<take; j+=32) s_nbr[off+j] = s_list[w][j];
  }
  __syncthreads();
  {
    int run = s_run;
    int pad = (run>0) ? s_nbr[0] : 0;
    for (int j=run+tx; j<NNEI; j+=256) s_nbr[j] = pad;
  }
  __syncthreads();

  for (int p=tx; p<NNEI; p+=blockDim.x) {
    float4 pt = g_p4[b*APTS + s_nbr[p]];
    float vx = pt.x-s_R[9], vy = pt.y-s_R[10], vz = pt.z-s_R[11];
    float t0 = s_R[0]*vx + s_R[1]*vy + s_R[2]*vz;
    float t1 = s_R[3]*vx + s_R[4]*vy + s_R[5]*vz;
    float t2 = s_R[6]*vx + s_R[7]*vy + s_R[8]*vz;
    s_t[p][0]=t0; s_t[p][1]=t1; s_t[p][2]=t2;
    bool ins = (t0>0.0f)&&(t0<0.3f)&&(t1>-0.15f)&&(t1<0.15f)&&(t2>-0.1f)&&(t2<0.1f);
    s_in[p] = ins ? 1 : 0;
  }
  __syncthreads();

  if (tx < 32) {
    int totI=0, first=-1;
    for (int ch=0; ch<NNEI/32; ch++) {
      int p = ch*32 + lane;
      bool ok = s_in[p]!=0;
      unsigned mm = __ballot_sync(0xffffffffu, ok);
      int app64 = totI<GNUM ? totI : GNUM;
      if (ok) {
        int pos = app64 + __popc(mm & ((1u<<lane)-1u));
        if (pos < GNUM) s_sel[pos] = p;
      }
      if (first<0 && mm) first = ch*32 + __ffs(mm)-1;
      totI += __popc(mm);
    }
    int cc64 = totI<GNUM ? totI : GNUM;
    int pad = (totI>0) ? first : 0;
    for (int j=lane; j<GNUM; j+=32) if (j>=cc64) s_sel[j]=pad;
    if (lane==0) s_ccount = cc64;
  }
  __syncthreads();

  for (int idx=tx; idx<GNUM*3; idx+=blockDim.x) {
    int n = idx/3, d = idx - n*3;
    g_gpts[g*(GNUM*3)+idx] = s_t[s_sel[n]][d];
  }
  if (tx==0) {
    bool mk = (s_totvalid>0) && (s_ccount>0) && (g_gmask[g]!=0);
    out[10240 + g] = mk ? 1.0f : 0.0f;
  }
}

// ---------------- fused MLP (layers 1-4) + heads, one block per grasp ----------------
// smem union layout (44032 B):
//   region LO  [0,10240):      h1 tile [64][72]bf16 | B3 [16][264]bf16 | B4 [32][136]bf16
//                              | f32 scratch [64][40] | head scratch (2000 f32)
//   region HI  [10240,44032):  B2 [64][264]bf16 | h2 [64][264]bf16 | h3 [64][264]bf16
//                              | out f32 [64][132]
#define PAD264 264
#define A4PAD 264
#define OPAD 132

__global__ void __launch_bounds__(256) mlp_fused_kernel(
  const float* __restrict__ W1, const float* __restrict__ b1,
  const float* __restrict__ b2, const float* __restrict__ b3, const float* __restrict__ b4,
  const float* __restrict__ stage1,
  const float* __restrict__ reg_w, const float* __restrict__ reg_b,
  const float* __restrict__ cls_w, const float* __restrict__ cls_b,
  const float* __restrict__ dc_reg_w, const float* __restrict__ dc_reg_b,
  const float* __restrict__ dc_cls_w, const float* __restrict__ dc_cls_b,
  float* __restrict__ out)
{
  __shared__ alignas(16) char s_u[44032];
  __shared__ float s_pts[GNUM*3];

  __nv_bfloat16* s_h1  = reinterpret_cast<__nv_bfloat16*>(s_u);            // [64][72]
  __nv_bfloat16* s_b3t = reinterpret_cast<__nv_bfloat16*>(s_u);            // [16][264]
  __nv_bfloat16* s_b4t = reinterpret_cast<__nv_bfloat16*>(s_u);            // [32][136]
  float*         s_scr = reinterpret_cast<float*>(s_u);                     // [64][40]
  float*         s_hd  = reinterpret_cast<float*>(s_u);                     // 2000 f
  __nv_bfloat16* s_b2t = reinterpret_cast<__nv_bfloat16*>(s_u + 10240);    // [64][264]
  __nv_bfloat16* s_h2  = reinterpret_cast<__nv_bfloat16*>(s_u + 10240);    // [64][264]
  __nv_bfloat16* s_h3  = reinterpret_cast<__nv_bfloat16*>(s_u + 10240);    // [64][264]
  float*         s_out = reinterpret_cast<float*>(s_u + 10240);            // [64][132]

  int tx = threadIdx.x;
  int g = blockIdx.x;
  int wid = tx >> 5, lane = tx & 31;
  if (tx < GNUM*3) s_pts[tx] = g_gpts[g*(GNUM*3)+tx];

  // ======== layer 1+2: acc2 = h1 @ W2t  (K=512, N=256) ========
  wmma::fragment<wmma::accumulator,16,16,16,float> acc8[8];
  #pragma unroll
  for (int f=0;f<8;f++) wmma::fill_fragment(acc8[f], 0.0f);
  int m0 = (wid & 3) * 16;
  int cIdx = wid >> 2;           // n-half 0/1
  int n0 = cIdx * 128;
  int kl = tx & 63;
  int nb = tx >> 6;
  __syncthreads();

  for (int kt=0; kt<8; kt++) {
    #pragma unroll
    for (int t=0;t<8;t++) {
      int idx = tx + 256*t;
      int r = idx >> 5, c8 = idx & 31;
      reinterpret_cast<uint4*>(s_b2t + r*PAD264)[c8] =
        reinterpret_cast<const uint4*>(g_W2tb + (kt*64 + r)*256)[c8];
    }
    int k = kt*64 + kl;
    float w0=W1[k*3], w1=W1[k*3+1], w2=W1[k*3+2], bb1=b1[k];
    #pragma unroll
    for (int t=0;t<16;t++) {
      int n = nb*16 + t;
      float v = fmaf(w2, s_pts[n*3+2], fmaf(w1, s_pts[n*3+1], fmaf(w0, s_pts[n*3+0], bb1)));
      s_h1[n*72 + kl] = __float2bfloat16(v>0.f ? v : 0.f);
    }
    __syncthreads();
    #pragma unroll
    for (int ks=0; ks<4; ks++) {
      wmma::fragment<wmma::matrix_a,16,16,16,__nv_bfloat16,wmma::row_major> fa;
      wmma::load_matrix_sync(fa, s_h1 + m0*72 + ks*16, 72);
      #pragma unroll
      for (int f=0;f<8;f++) {
        wmma::fragment<wmma::matrix_b,16,16,16,__nv_bfloat16,wmma::row_major> fb;
        wmma::load_matrix_sync(fb, s_b2t + (ks*16)*PAD264 + n0 + 16*f, PAD264);
        wmma::mma_sync(acc8[f], fa, fb, acc8[f]);
      }
    }
    __syncthreads();
  }

  // acc8 -> s_h2 = bf16(relu(acc + b2)), via f32 scratch [64][2][20]
  for (int f=0; f<8; f++) {
    wmma::store_matrix_sync(s_scr + m0*40 + cIdx*20, acc8[f], 40, wmma::mem_row_major);
    __syncthreads();
    for (int idx=tx; idx<2048; idx+=256) {
      int n = idx>>5, c = idx&31;
      int cb = c>>4, ccl = c&15;
      float v = s_scr[n*40 + cb*20 + ccl];
      int o = cb*128 + f*16 + ccl;
      v += b2[o]; v = v>0.f ? v : 0.f;
      s_h2[n*PAD264 + o] = __float2bfloat16(v);
    }
    __syncthreads();
  }

  // ======== layer 3: acc = h2 @ W3t  (K=256, N=256), B chunk 16 ========
  #pragma unroll
  for (int f=0;f<8;f++) wmma::fill_fragment(acc8[f], 0.0f);
  for (int kt=0; kt<16; kt++) {
    #pragma unroll
    for (int t=0;t<2;t++) {
      int idx = tx + 256*t;
      int r = idx >> 5, c8 = idx & 31;
      reinterpret_cast<uint4*>(s_b3t + r*PAD264)[c8] =
        reinterpret_cast<const uint4*>(g_W3tb + (kt*16 + r)*256)[c8];
    }
    __syncthreads();
    {
      wmma::fragment<wmma::matrix_a,16,16,16,__nv_bfloat16,wmma::row_major> fa;
      wmma::load_matrix_sync(fa, s_h2 + m0*PAD264 + kt*16, PAD264);
      #pragma unroll
      for (int f=0;f<8;f++) {
        wmma::fragment<wmma::matrix_b,16,16,16,__nv_bfloat16,wmma::row_major> fb;
        wmma::load_matrix_sync(fb, s_b3t + n0 + 16*f, PAD264);
        wmma::mma_sync(acc8[f], fa, fb, acc8[f]);
      }
    }
    __syncthreads();
  }

  // acc8 -> s_h3 = bf16(relu(acc + b3))  (overwrites s_h2 region)
  for (int f=0; f<8; f++) {
    wmma::store_matrix_sync(s_scr + m0*40 + cIdx*20, acc8[f], 40, wmma::mem_row_major);
    __syncthreads();
    for (int idx=tx; idx<2048; idx+=256) {
      int n = idx>>5, c = idx&31;
      int cb = c>>4, ccl = c&15;
      float v = s_scr[n*40 + cb*20 + ccl];
      int o = cb*128 + f*16 + ccl;
      v += b3[o]; v = v>0.f ? v : 0.f;
      s_h3[n*A4PAD + o] = __float2bfloat16(v);
    }
    __syncthreads();
  }

  // ======== layer 4: acc4 = h3 @ W4t  (K=256, N=128), B chunk 32 ========
  wmma::fragment<wmma::accumulator,16,16,16,float> acc4[4];
  #pragma unroll
  for (int f=0;f<4;f++) wmma::fill_fragment(acc4[f], 0.0f);
  int n40 = cIdx * 64;
  for (int kt=0; kt<8; kt++) {
    #pragma unroll
    for (int t=0;t<2;t++) {
      int idx = tx + 256*t;
      int r = idx >> 4, c8 = idx & 15;
      reinterpret_cast<uint4*>(s_b4t + r*136)[c8] =
        reinterpret_cast<const uint4*>(g_W4tb + (kt*32 + r)*128)[c8];
    }
    __syncthreads();
    #pragma unroll
    for (int ks=0; ks<2; ks++) {
      wmma::fragment<wmma::matrix_a,16,16,16,__nv_bfloat16,wmma::row_major> fa;
      wmma::load_matrix_sync(fa, s_h3 + m0*A4PAD + kt*32 + ks*16, A4PAD);
      #pragma unroll
      for (int f=0;f<4;f++) {
        wmma::fragment<wmma::matrix_b,16,16,16,__nv_bfloat16,wmma::row_major> fb;
        wmma::load_matrix_sync(fb, s_b4t + (ks*16)*136 + n40 + 16*f, 136);
        wmma::mma_sync(acc4[f], fa, fb, acc4[f]);
      }
    }
    __syncthreads();
  }
  // s_h3 dead -> store raw acc to s_out (overlaps s_h3)
  #pragma unroll
  for (int f=0;f<4;f++)
    wmma::store_matrix_sync(s_out + m0*OPAD + n40 + 16*f, acc4[f], OPAD, wmma::mem_row_major);

  // ======== heads ========
  float* s_dc  = s_hd;          // 640
  float* s_rw2 = s_hd + 640;    // 1280
  float* s_pt  = s_hd + 1920;   // 80
  for (int i=tx;i<512;i+=256) s_dc[i]     = dc_reg_w[i];
  for (int i=tx;i<128;i+=256) s_dc[512+i] = dc_cls_w[i];
  for (int i=tx;i<1280;i+=256) {
    int c = i>>7, j = i&127;
    s_rw2[i] = (c<8) ? reg_w[c*384 + 256 + j] : cls_w[(c-8)*384 + 256 + j];
  }
  __syncthreads();

  int hn0 = wid*8, j0 = lane*4;
  float bj[4];
  #pragma unroll
  for (int q=0;q<4;q++) bj[q] = b4[j0+q];
  #pragma unroll
  for (int c=0;c<10;c++) {
    const float* dcw = (c<8) ? (s_dc + c*64) : (s_dc + 512 + (c-8)*64);
    const float* rw2 = s_rw2 + c*128 + j0;
    float pc_ = 0.f;
    #pragma unroll
    for (int i=0;i<8;i++) {
      float t = 0.f;
      #pragma unroll
      for (int q=0;q<4;q++) {
        float h = s_out[(hn0+i)*OPAD + j0+q] + bj[q];
        h = h>0.f ? h : 0.f;
        t = fmaf(rw2[q], h, t);
      }
      pc_ = fmaf(dcw[hn0+i], t, pc_);
    }
    #pragma unroll
    for (int off=16; off>0; off>>=1) pc_ += __shfl_down_sync(0xffffffffu, pc_, off);
    if (lane==0) s_pt[c*8 + wid] = pc_;
  }
  __syncthreads();

  for (int c = wid; c < 10; c += 8) {
    float hd = (lane < 8) ? s_pt[c*8 + lane] : 0.f;
    const float* rw = (c<8) ? (reg_w + c*384) : (cls_w + (c-8)*384);
    const float* s1 = stage1 + g*256;
    float s1d = 0.f;
    #pragma unroll
    for (int t=0;t<8;t++) {
      int j = lane + 32*t;
      s1d = fmaf(rw[j], s1[j], s1d);
    }
    const float* dcw = (c<8) ? (s_dc + c*64) : (s_dc + 512 + (c-8)*64);
    float S = dcw[lane] + dcw[lane+32];
    #pragma unroll
    for (int off=16; off>0; off>>=1) {
      hd  += __shfl_down_sync(0xffffffffu, hd,  off);
      s1d += __shfl_down_sync(0xffffffffu, s1d, off);
      S   += __shfl_down_sync(0xffffffffu, S,   off);
    }
    if (lane==0) {
      float bc  = (c<8) ? reg_b[c] : cls_b[c-8];
      float dcb = (c<8) ? dc_reg_b[c] : dc_cls_b[c-8];
      float o = hd + (s1d + bc)*S + dcb;
      if (c < 8) out[2048 + g*8 + c] = o;
      else       out[g*2 + (c-8)]   = o;
    }
  }
}

// ---------------- launch ----------------

extern "C" void kernel_launch(void* const* d_in, const int* in_sizes, int n_in,
                              void* d_out, int out_size) {
  const float* grasp  = (const float*)d_in[0];
  const float* pc     = (const float*)d_in[1];
  const float* stage1 = (const float*)d_in[3];
  const float* W1 = (const float*)d_in[4];  const float* b1 = (const float*)d_in[5];
  const float* W2 = (const float*)d_in[6];  const float* b2 = (const float*)d_in[7];
  const float* W3 = (const float*)d_in[8];  const float* b3 = (const float*)d_in[9];
  const float* W4 = (const float*)d_in[10]; const float* b4 = (const float*)d_in[11];
  const float* reg_w = (const float*)d_in[12]; const float* reg_b = (const float*)d_in[13];
  const float* cls_w = (const float*)d_in[14]; const float* cls_b = (const float*)d_in[15];
  const float* dcrw  = (const float*)d_in[16]; const float* dcrb  = (const float*)d_in[17];
  const float* dccw  = (const float*)d_in[18]; const float* dccb  = (const float*)d_in[19];
  float* out = (float*)d_out;

  prep_points<<<(BATCH*APTS + 255)/256, 256>>>(pc);
  prep_grasp<<<(BN + 255)/256, 256>>>(grasp);
  transpose_w<<<(512*256 + 256*256 + 256*128 + 255)/256, 256>>>(W2, W3, W4);
  bq_kernel<<<BN, 256>>>(grasp, out);
  mlp_fused_kernel<<<BN, 256>>>(W1, b1, b2, b3, b4, stage1,
                                reg_w, reg_b, cls_w, cls_b,
                                dcrw, dcrb, dccw, dccb, out);
}